// round 5
// baseline (speedup 1.0000x reference)
#include <cuda_runtime.h>

#define NPTS    2048
#define UPR     10
#define NJIT    (NPTS*UPR)           // 20480 jittered queries
#define QTOT    (NJIT + NPTS)        // 22528
#define KNN     5
#define GSZ     16                   // points per group
#define NG      (NPTS/GSZ)           // 128 groups
#define T1      256                  // main kernel block (128 queries, SPLIT=2)
#define QPB     (T1/2)               // 128
#define NBJ     (NJIT/QPB)           // 160 jitter blocks
#define NBS     (NPTS/QPB)           // 16 src-query blocks
#define NB1     (NBJ+NBS)            // 176
#define EPS_D   1e-8f
#define EPS_N   1e-10f
#define BETA    3.0f
#define STDV    0.05f
#define IDXMASK 0xFFFFF800u          // high 21 bits = d2, low 11 = sorted index

// Sorted clouds + group metadata. [0]=tgt, [1]=src.
__device__ float4 g_pts[2][NPTS];      // {x,y,z,|p|^2} Morton-sorted
__device__ int    g_id[2][NPTS];       // original index
__device__ float4 g_grp[2][NG];        // {cx,cy,cz,|c|^2}
__device__ float  g_rad[2][NG];        // bounding radius
__device__ int    g_seedTS[NPTS];      // nearest src group per sorted tgt point
__device__ int    g_seedST[NPTS];      // nearest tgt group per sorted src point
__device__ float  g_partial[NB1];

// ---------------------------------------------------------------- prep: sort
__device__ __forceinline__ unsigned expand10(unsigned v) {
    v &= 0x3FFu;
    v = (v | (v << 16)) & 0x030000FFu;
    v = (v | (v << 8))  & 0x0300F00Fu;
    v = (v | (v << 4))  & 0x030C30C3u;
    v = (v | (v << 2))  & 0x09249249u;
    return v;
}

__global__ __launch_bounds__(1024)
void prep_sort(const float* __restrict__ src, const float* __restrict__ tgt)
{
    __shared__ unsigned long long sk[NPTS];
    const int cloud = blockIdx.x;
    const float* __restrict__ pts = cloud ? src : tgt;
    const int tid = threadIdx.x;

    for (int i = tid; i < NPTS; i += 1024) {
        float x = pts[3*i], y = pts[3*i+1], z = pts[3*i+2];
        unsigned xi = (unsigned)fminf(fmaxf((x + 5.0f) * 102.4f, 0.0f), 1023.0f);
        unsigned yi = (unsigned)fminf(fmaxf((y + 5.0f) * 102.4f, 0.0f), 1023.0f);
        unsigned zi = (unsigned)fminf(fmaxf((z + 5.0f) * 102.4f, 0.0f), 1023.0f);
        unsigned code = (expand10(zi) << 2) | (expand10(yi) << 1) | expand10(xi);
        sk[i] = ((unsigned long long)code << 11) | (unsigned)i;
    }

    // Bitonic sort, 2048 elements.
    for (int k = 2; k <= NPTS; k <<= 1) {
        for (int j = k >> 1; j > 0; j >>= 1) {
            __syncthreads();
#pragma unroll
            for (int s = 0; s < 2; ++s) {
                int i = tid + s * 1024;
                int l = i ^ j;
                if (l > i) {
                    bool up = ((i & k) == 0);
                    unsigned long long a = sk[i], b = sk[l];
                    if ((a > b) == up) { sk[i] = b; sk[l] = a; }
                }
            }
        }
    }
    __syncthreads();

    for (int i = tid; i < NPTS; i += 1024) {
        int oi = (int)(sk[i] & 2047ull);
        float x = pts[3*oi], y = pts[3*oi+1], z = pts[3*oi+2];
        g_pts[cloud][i] = make_float4(x, y, z, fmaf(x, x, fmaf(y, y, z * z)));
        g_id[cloud][i]  = oi;
    }

    if (tid < NG) {
        float mnx = 3e38f, mny = 3e38f, mnz = 3e38f;
        float mxx = -3e38f, mxy = -3e38f, mxz = -3e38f;
        for (int j = 0; j < GSZ; ++j) {
            int oi = (int)(sk[tid * GSZ + j] & 2047ull);
            float x = pts[3*oi], y = pts[3*oi+1], z = pts[3*oi+2];
            mnx = fminf(mnx, x); mxx = fmaxf(mxx, x);
            mny = fminf(mny, y); mxy = fmaxf(mxy, y);
            mnz = fminf(mnz, z); mxz = fmaxf(mxz, z);
        }
        float cx = 0.5f * (mnx + mxx), cy = 0.5f * (mny + mxy), cz = 0.5f * (mnz + mxz);
        float hx = 0.5f * (mxx - mnx), hy = 0.5f * (mxy - mny), hz = 0.5f * (mxz - mnz);
        g_grp[cloud][tid] = make_float4(cx, cy, cz, fmaf(cx, cx, fmaf(cy, cy, cz * cz)));
        g_rad[cloud][tid] = sqrtf(fmaf(hx, hx, fmaf(hy, hy, hz * hz)));
    }
}

// ------------------------------------------------------------- prep: seeds
__global__ __launch_bounds__(256)
void prep_seed()
{
    const int idx = blockIdx.x * 256 + threadIdx.x;   // point index
    const int dir = blockIdx.y;                        // 0: tgt->srcGrp, 1: src->tgtGrp
    float4 p = g_pts[dir ? 1 : 0][idx];
    const int gc = dir ? 0 : 1;
    float best = 3e38f; int bi = 0;
    for (int g = 0; g < NG; ++g) {
        float4 c = g_grp[gc][g];
        float dx = p.x - c.x, dy = p.y - c.y, dz = p.z - c.z;
        float d2 = fmaf(dx, dx, fmaf(dy, dy, dz * dz));
        if (d2 < best) { best = d2; bi = g; }
    }
    if (dir == 0) g_seedTS[idx] = bi; else g_seedST[idx] = bi;
}

// ------------------------------------------------------------------- main
__device__ __forceinline__ void ins5key(int key, int& s0, int& s1, int& s2, int& s3, int& s4) {
    s4 = key;
    int a;
    a = min(s3, s4); s4 = max(s3, s4); s3 = a;
    a = min(s2, s3); s3 = max(s2, s3); s2 = a;
    a = min(s1, s2); s2 = max(s1, s2); s1 = a;
    a = min(s0, s1); s1 = max(s0, s1); s0 = a;
}

// Scan one cloud with group pruning. Returns normalized weighted gradient
// (valid in leader lane par==0 only).
__device__ __forceinline__ float4 scan_cloud(
    const float4* __restrict__ gp,
    const float4* __restrict__ sG, const float* __restrict__ sR,
    int seedg, int par,
    float qx, float qy, float qz,
    float qx2, float qy2, float qz2, float q2)
{
    int s0 = 0x7F000000, s1 = 0x7F000001, s2 = 0x7F000002,
        s3 = 0x7F000003, s4 = 0x7F000004;
    float th  = __int_as_float(s4);
    float thr = th - q2;
    float A2  = 2.0f * sqrtf(th);

    // Seed group: both lanes, split by point parity.
    {
        int b = seedg * GSZ;
#pragma unroll
        for (int jj = par; jj < GSZ; jj += 2) {
            float4 p = gp[b + jj];
            float r = fmaf(p.x, qx2, fmaf(p.y, qy2, fmaf(p.z, qz2, p.w)));
            if (r < thr) {
                float d2 = fmaxf(r + q2, 0.0f);
                int key = (int)((__float_as_uint(d2) & IDXMASK) | (unsigned)(b + jj));
                ins5key(key, s0, s1, s2, s3, s4);
                th = __int_as_float(s4); thr = th - q2; A2 = 2.0f * sqrtf(th);
            }
        }
    }

    // Main loop: this lane owns groups gi % 2 == par (seed group excluded).
    for (int gi = par; gi < NG; gi += 2) {
        if (gi == seedg) continue;
        float4 c = sG[gi];
        float rd = sR[gi];
        float rc = fmaf(c.x, qx2, fmaf(c.y, qy2, fmaf(c.z, qz2, c.w)));
        if (rc <= fmaf(rd, rd + A2, thr)) {
            int b = gi * GSZ;
#pragma unroll 4
            for (int jj = 0; jj < GSZ; ++jj) {
                float4 p = gp[b + jj];
                float r = fmaf(p.x, qx2, fmaf(p.y, qy2, fmaf(p.z, qz2, p.w)));
                if (r < thr) {
                    float d2 = fmaxf(r + q2, 0.0f);
                    int key = (int)((__float_as_uint(d2) & IDXMASK) | (unsigned)(b + jj));
                    ins5key(key, s0, s1, s2, s3, s4);
                    th = __int_as_float(s4); thr = th - q2; A2 = 2.0f * sqrtf(th);
                }
            }
        }
    }

    // Merge partner lane (disjoint point sets).
    {
        int o0 = __shfl_xor_sync(0xFFFFFFFFu, s0, 1);
        int o1 = __shfl_xor_sync(0xFFFFFFFFu, s1, 1);
        int o2 = __shfl_xor_sync(0xFFFFFFFFu, s2, 1);
        int o3 = __shfl_xor_sync(0xFFFFFFFFu, s3, 1);
        int o4 = __shfl_xor_sync(0xFFFFFFFFu, s4, 1);
        if (o0 < s4) ins5key(o0, s0, s1, s2, s3, s4);
        if (o1 < s4) ins5key(o1, s0, s1, s2, s3, s4);
        if (o2 < s4) ins5key(o2, s0, s1, s2, s3, s4);
        if (o3 < s4) ins5key(o3, s0, s1, s2, s3, s4);
        if (o4 < s4) ins5key(o4, s0, s1, s2, s3, s4);
    }

    float4 out = make_float4(0.f, 0.f, 0.f, 0.f);
    if (par == 0) {
        float aw = 0.f, gx = 0.f, gy = 0.f, gz = 0.f;
        int keys[KNN] = {s0, s1, s2, s3, s4};
#pragma unroll
        for (int k = 0; k < KNN; ++k) {
            int idx = keys[k] & 2047;
            float4 p = gp[idx];
            float r  = fmaf(p.x, qx2, fmaf(p.y, qy2, fmaf(p.z, qz2, p.w)));
            float d2 = fmaxf(r + q2, 0.0f);
            float w  = 1.0f / (d2 + EPS_D);
            aw += w;
            gx = fmaf(qx - p.x, w, gx);
            gy = fmaf(qy - p.y, w, gy);
            gz = fmaf(qz - p.z, w, gz);
        }
        float inv = 1.0f / aw;
        out = make_float4(gx * inv, gy * inv, gz * inv, 0.f);
    }
    return out;
}

__global__ __launch_bounds__(T1)
void knn_main(const float* __restrict__ noise)
{
    __shared__ float4 sGT[NG], sGS[NG];
    __shared__ float  sRT[NG], sRS[NG];
    __shared__ float  red[T1 / 32];

    const int tid = threadIdx.x;
    if (tid < NG) {
        sGT[tid] = g_grp[0][tid]; sRT[tid] = g_rad[0][tid];
        sGS[tid] = g_grp[1][tid]; sRS[tid] = g_rad[1][tid];
    }
    __syncthreads();

    const int b   = blockIdx.x;
    const int ql  = tid >> 1;
    const int par = tid & 1;

    float qx, qy, qz;
    int seedT, seedS;
    if (b < NBJ) {
        int g  = b * QPB + ql;      // jitter index in sorted-parent order
        int sp = g / UPR;
        int u  = g - sp * UPR;
        float4 pp = g_pts[0][sp];
        int m  = g_id[0][sp];
        int nb = (m * UPR + u) * 3;
        qx = fmaf(noise[nb + 0], STDV, pp.x);
        qy = fmaf(noise[nb + 1], STDV, pp.y);
        qz = fmaf(noise[nb + 2], STDV, pp.z);
        seedT = sp >> 4;
        seedS = g_seedTS[sp];
    } else {
        int sq = (b - NBJ) * QPB + ql;
        float4 pp = g_pts[1][sq];
        qx = pp.x; qy = pp.y; qz = pp.z;
        seedT = g_seedST[sq];
        seedS = sq >> 4;
    }
    const float qx2 = -2.0f * qx, qy2 = -2.0f * qy, qz2 = -2.0f * qz;
    const float q2  = fmaf(qx, qx, fmaf(qy, qy, qz * qz));

    float4 gT = scan_cloud(g_pts[0], sGT, sRT, seedT, par, qx, qy, qz, qx2, qy2, qz2, q2);
    float4 gS = scan_cloud(g_pts[1], sGS, sRS, seedS, par, qx, qy, qz, qx2, qy2, qz2, q2);

    float contrib = 0.f;
    if (par == 0) {
        float axT = gT.x + EPS_N, ayT = gT.y + EPS_N, azT = gT.z + EPS_N;
        float axS = gS.x + EPS_N, ayS = gS.y + EPS_N, azS = gS.z + EPS_N;
        float uT = sqrtf(fmaf(axT, axT, fmaf(ayT, ayT, azT * azT)));
        float uS = sqrtf(fmaf(axS, axS, fmaf(ayS, ayS, azS * azS)));
        float e1 = fabsf(uT - uS);
        float e2 = fabsf(gS.x - gT.x) + fabsf(gS.y - gT.y) + fabsf(gS.z - gT.z);
        float t  = e1 + e2;
        contrib  = t * __expf(-BETA * t);
    }

#pragma unroll
    for (int o = 16; o > 0; o >>= 1)
        contrib += __shfl_down_sync(0xFFFFFFFFu, contrib, o);
    if ((tid & 31) == 0) red[tid >> 5] = contrib;
    __syncthreads();
    if (tid == 0) {
        float s = 0.f;
#pragma unroll
        for (int w = 0; w < T1 / 32; ++w) s += red[w];
        g_partial[b] = s;
    }
}

__global__ void final_reduce(float* __restrict__ out)
{
    __shared__ float sh[8];
    int tid = threadIdx.x;   // 256
    float v = (tid < NB1) ? g_partial[tid] : 0.f;
#pragma unroll
    for (int o = 16; o > 0; o >>= 1) v += __shfl_down_sync(0xFFFFFFFFu, v, o);
    if ((tid & 31) == 0) sh[tid >> 5] = v;
    __syncthreads();
    if (tid == 0) {
        float s = 0.f;
#pragma unroll
        for (int w = 0; w < 8; ++w) s += sh[w];
        out[0] = s * (1.0f / (float)QTOT);
    }
}

extern "C" void kernel_launch(void* const* d_in, const int* in_sizes, int n_in,
                              void* d_out, int out_size)
{
    const float* src   = (const float*)d_in[0];
    const float* tgt   = (const float*)d_in[1];
    const float* noise = (const float*)d_in[2];
    (void)in_sizes; (void)n_in; (void)out_size;

    prep_sort<<<2, 1024>>>(src, tgt);
    prep_seed<<<dim3(NPTS / 256, 2), 256>>>();
    knn_main<<<NB1, T1>>>(noise);
    final_reduce<<<1, 256>>>((float*)d_out);
}

// round 6
// speedup vs baseline: 2.3310x; 2.3310x over previous
#include <cuda_runtime.h>

#define NPTS    2048
#define UPR     10
#define NJIT    (NPTS*UPR)           // 20480 jittered queries
#define QTOT    (NJIT + NPTS)        // 22528
#define KNN     5
#define T1      256
#define SPLIT   4
#define QPB     (T1/SPLIT)           // 64 queries per block
#define NQA     (2*NPTS)             // stage-A queries: tgt parents + src points
#define GXA     (NQA/QPB)            // 64
#define GXB     (NJIT/QPB)           // 320
#define NB2     (QTOT/256)           // 88
#define EPS_D   1e-8f
#define EPS_N   1e-10f
#define BETA    3.0f
#define STDV    0.05f
#define IDXMASK 0xFFFFF800u          // high 21 bits = d2, low 11 bits = point index

__device__ float4 g_grad[2][QTOT];   // normalized weighted gradient per (cloud,query)
__device__ float  g_d5[2][NPTS];     // 5NN distance bound for tgt parents, per cloud
__device__ float  g_partial[NB2];

__device__ __forceinline__ void ins5key(int key, int& s0, int& s1, int& s2, int& s3, int& s4) {
    s4 = key;
    int a;
    a = min(s3, s4); s4 = max(s3, s4); s3 = a;
    a = min(s2, s3); s3 = max(s2, s3); s2 = a;
    a = min(s1, s2); s2 = max(s1, s2); s1 = a;
    a = min(s0, s1); s1 = max(s0, s1); s0 = a;
}

__device__ __forceinline__ void merge_keys(int msk, int& s0, int& s1, int& s2, int& s3, int& s4) {
    int o0 = __shfl_xor_sync(0xFFFFFFFFu, s0, msk);
    int o1 = __shfl_xor_sync(0xFFFFFFFFu, s1, msk);
    int o2 = __shfl_xor_sync(0xFFFFFFFFu, s2, msk);
    int o3 = __shfl_xor_sync(0xFFFFFFFFu, s3, msk);
    int o4 = __shfl_xor_sync(0xFFFFFFFFu, s4, msk);
    if (o0 < s4) ins5key(o0, s0, s1, s2, s3, s4);
    if (o1 < s4) ins5key(o1, s0, s1, s2, s3, s4);
    if (o2 < s4) ins5key(o2, s0, s1, s2, s3, s4);
    if (o3 < s4) ins5key(o3, s0, s1, s2, s3, s4);
    if (o4 < s4) ins5key(o4, s0, s1, s2, s3, s4);
}

// Leader-lane epilogue: exact weighted gradient from the 5 packed keys.
__device__ __forceinline__ float4 grad_from_keys(
    const float4* __restrict__ sC, int s0, int s1, int s2, int s3, int s4,
    float qx, float qy, float qz, float qx2, float qy2, float qz2, float q2)
{
    float aw = 0.f, gx = 0.f, gy = 0.f, gz = 0.f;
    int keys[KNN] = {s0, s1, s2, s3, s4};
#pragma unroll
    for (int k = 0; k < KNN; ++k) {
        int idx = keys[k] & 2047;
        float4 p = sC[idx];
        float r  = fmaf(p.x, qx2, fmaf(p.y, qy2, fmaf(p.z, qz2, p.w)));
        float d2 = fmaxf(r + q2, 0.0f);
        float w  = 1.0f / (d2 + EPS_D);
        aw += w;
        gx = fmaf(qx - p.x, w, gx);
        gy = fmaf(qy - p.y, w, gy);
        gz = fmaf(qz - p.z, w, gz);
    }
    float inv = 1.0f / aw;
    return make_float4(gx * inv, gy * inv, gz * inv, 0.f);
}

__device__ __forceinline__ void load_cloud(const float* __restrict__ pts, float4* sC, int tid) {
    for (int i = tid; i < NPTS; i += T1) {
        float x = pts[3*i], y = pts[3*i+1], z = pts[3*i+2];
        sC[i] = make_float4(x, y, z, fmaf(x, x, fmaf(y, y, z * z)));
    }
}

// ---------------- Stage A: cloud-points-as-queries (cold thresholds) --------
__global__ __launch_bounds__(T1)
void knn_seed(const float* __restrict__ src, const float* __restrict__ tgt)
{
    __shared__ float4 sC[NPTS];
    const int tid   = threadIdx.x;
    const int cloud = blockIdx.y;
    load_cloud(cloud ? src : tgt, sC, tid);
    __syncthreads();

    const int qa  = blockIdx.x * QPB + (tid >> 2);  // 0..4095
    const int par = tid & 3;

    float qx, qy, qz;
    if (qa < NPTS) { qx = tgt[3*qa];          qy = tgt[3*qa+1];          qz = tgt[3*qa+2]; }
    else           { int m = qa - NPTS; qx = src[3*m]; qy = src[3*m+1]; qz = src[3*m+2]; }
    const float qx2 = -2.0f * qx, qy2 = -2.0f * qy, qz2 = -2.0f * qz;
    const float q2  = fmaf(qx, qx, fmaf(qy, qy, qz * qz));

    int s0 = 0x7F000000, s1 = 0x7F000001, s2 = 0x7F000002,
        s3 = 0x7F000003, s4 = 0x7F000004;
    float thr = __int_as_float(s4) - q2;

#pragma unroll 8
    for (int jj = 0; jj < NPTS / SPLIT; ++jj) {
        int j = (jj << 2) + par;
        float4 p = sC[j];
        float r  = fmaf(p.x, qx2, fmaf(p.y, qy2, fmaf(p.z, qz2, p.w)));
        if (r < thr) {
            float d2 = fmaxf(r + q2, 0.0f);
            int key = (int)((__float_as_uint(d2) & IDXMASK) | (unsigned)j);
            ins5key(key, s0, s1, s2, s3, s4);
            thr = __int_as_float(s4) - q2;
        }
    }

    merge_keys(1, s0, s1, s2, s3, s4);
    merge_keys(2, s0, s1, s2, s3, s4);

    if (par == 0) {
        if (qa < NPTS) {
            // parent 5NN distance bound (junk low bits only inflate -> conservative)
            g_d5[cloud][qa] = sqrtf(fmaxf(__int_as_float(s4), 0.0f));
        } else {
            float4 g = grad_from_keys(sC, s0, s1, s2, s3, s4, qx, qy, qz, qx2, qy2, qz2, q2);
            g_grad[cloud][NJIT + (qa - NPTS)] = g;
        }
    }
}

// ---------------- Stage B: jittered queries (warm thresholds) --------------
__global__ __launch_bounds__(T1)
void knn_jit(const float* __restrict__ src, const float* __restrict__ tgt,
             const float* __restrict__ noise)
{
    __shared__ float4 sC[NPTS];
    const int tid   = threadIdx.x;
    const int cloud = blockIdx.y;
    load_cloud(cloud ? src : tgt, sC, tid);
    __syncthreads();

    const int qi  = blockIdx.x * QPB + (tid >> 2);  // 0..NJIT-1
    const int par = tid & 3;

    const int m  = qi / UPR;
    float nx = noise[3*qi + 0], ny = noise[3*qi + 1], nz = noise[3*qi + 2];
    float px = tgt[3*m], py = tgt[3*m+1], pz = tgt[3*m+2];
    float qx = fmaf(nx, STDV, px);
    float qy = fmaf(ny, STDV, py);
    float qz = fmaf(nz, STDV, pz);
    const float qx2 = -2.0f * qx, qy2 = -2.0f * qy, qz2 = -2.0f * qz;
    const float q2  = fmaf(qx, qx, fmaf(qy, qy, qz * qz));

    // Warm threshold: (d5(parent) + |q - parent|)^2, slightly inflated.
    float delta = STDV * sqrtf(fmaf(nx, nx, fmaf(ny, ny, nz * nz)));
    float THd   = g_d5[cloud][m] + delta;
    float TH2   = fmaf(THd, THd, 1e-7f) * 1.001f;
    int th_key  = (int)((__float_as_uint(TH2) & IDXMASK) | 0x7FFu);

    int s0 = th_key, s1 = th_key, s2 = th_key, s3 = th_key, s4 = th_key;
    float thr = __int_as_float(th_key) - q2;

#pragma unroll 8
    for (int jj = 0; jj < NPTS / SPLIT; ++jj) {
        int j = (jj << 2) + par;
        float4 p = sC[j];
        float r  = fmaf(p.x, qx2, fmaf(p.y, qy2, fmaf(p.z, qz2, p.w)));
        if (r < thr) {
            float d2 = fmaxf(r + q2, 0.0f);
            int key = (int)((__float_as_uint(d2) & IDXMASK) | (unsigned)j);
            ins5key(key, s0, s1, s2, s3, s4);
            thr = __int_as_float(s4) - q2;
        }
    }

    merge_keys(1, s0, s1, s2, s3, s4);
    merge_keys(2, s0, s1, s2, s3, s4);

    if (par == 0) {
        float4 g = grad_from_keys(sC, s0, s1, s2, s3, s4, qx, qy, qz, qx2, qy2, qz2, q2);
        g_grad[cloud][qi] = g;
    }
}

// ---------------- tails ------------------------------------------------------
__global__ __launch_bounds__(256)
void combine_kernel()
{
    __shared__ float sh[8];
    const int tid = threadIdx.x;
    const int qi  = blockIdx.x * 256 + tid;

    float4 gT = g_grad[0][qi];
    float4 gS = g_grad[1][qi];

    float axT = gT.x + EPS_N, ayT = gT.y + EPS_N, azT = gT.z + EPS_N;
    float axS = gS.x + EPS_N, ayS = gS.y + EPS_N, azS = gS.z + EPS_N;
    float uT = sqrtf(fmaf(axT, axT, fmaf(ayT, ayT, azT * azT)));
    float uS = sqrtf(fmaf(axS, axS, fmaf(ayS, ayS, azS * azS)));

    float e1 = fabsf(uT - uS);
    float e2 = fabsf(gS.x - gT.x) + fabsf(gS.y - gT.y) + fabsf(gS.z - gT.z);
    float t  = e1 + e2;
    float v  = t * __expf(-BETA * t);

#pragma unroll
    for (int o = 16; o > 0; o >>= 1) v += __shfl_down_sync(0xFFFFFFFFu, v, o);
    if ((tid & 31) == 0) sh[tid >> 5] = v;
    __syncthreads();
    if (tid == 0) {
        float s = 0.f;
#pragma unroll
        for (int w = 0; w < 8; ++w) s += sh[w];
        g_partial[blockIdx.x] = s;
    }
}

__global__ void final_reduce(float* __restrict__ out)
{
    __shared__ float sh[4];
    int tid = threadIdx.x;   // 128
    float v = (tid < NB2) ? g_partial[tid] : 0.f;
#pragma unroll
    for (int o = 16; o > 0; o >>= 1) v += __shfl_down_sync(0xFFFFFFFFu, v, o);
    if ((tid & 31) == 0) sh[tid >> 5] = v;
    __syncthreads();
    if (tid == 0) {
        float s = sh[0] + sh[1] + sh[2] + sh[3];
        out[0] = s * (1.0f / (float)QTOT);
    }
}

extern "C" void kernel_launch(void* const* d_in, const int* in_sizes, int n_in,
                              void* d_out, int out_size)
{
    const float* src   = (const float*)d_in[0];
    const float* tgt   = (const float*)d_in[1];
    const float* noise = (const float*)d_in[2];
    (void)in_sizes; (void)n_in; (void)out_size;

    knn_seed<<<dim3(GXA, 2), T1>>>(src, tgt);
    knn_jit <<<dim3(GXB, 2), T1>>>(src, tgt, noise);
    combine_kernel<<<NB2, 256>>>();
    final_reduce<<<1, 128>>>((float*)d_out);
}

// round 7
// speedup vs baseline: 2.9152x; 1.2506x over previous
#include <cuda_runtime.h>

#define NPTS    2048
#define NPAIR   (NPTS/2)             // 1024 point-pairs
#define UPR     10
#define NJIT    (NPTS*UPR)           // 20480 jittered queries
#define QTOT    (NJIT + NPTS)        // 22528
#define KNN     5
#define T1      256
#define SPLIT   4
#define QPB     (T1/SPLIT)           // 64 queries per block
#define GX1     (QTOT/QPB)           // 352  (x2 clouds in grid.y)
#define NB2     (QTOT/256)           // 88
#define EPS_D   1e-8f
#define EPS_N   1e-10f
#define BETA    3.0f
#define STDV    0.05f
#define IDXMASK 0xFFFFF800u          // high 21 bits = d2, low 11 bits = point index

__device__ float4 g_grad[2][QTOT];   // normalized weighted gradient per (cloud,query)
__device__ float  g_partial[NB2];

__device__ __forceinline__ void ins5key(int key, int& s0, int& s1, int& s2, int& s3, int& s4) {
    s4 = key;
    int a;
    a = min(s3, s4); s4 = max(s3, s4); s3 = a;
    a = min(s2, s3); s3 = max(s2, s3); s2 = a;
    a = min(s1, s2); s2 = max(s1, s2); s1 = a;
    a = min(s0, s1); s1 = max(s0, s1); s0 = a;
}

__device__ __forceinline__ void merge_keys(int msk, int& s0, int& s1, int& s2, int& s3, int& s4) {
    int o0 = __shfl_xor_sync(0xFFFFFFFFu, s0, msk);
    int o1 = __shfl_xor_sync(0xFFFFFFFFu, s1, msk);
    int o2 = __shfl_xor_sync(0xFFFFFFFFu, s2, msk);
    int o3 = __shfl_xor_sync(0xFFFFFFFFu, s3, msk);
    int o4 = __shfl_xor_sync(0xFFFFFFFFu, s4, msk);
    if (o0 < s4) ins5key(o0, s0, s1, s2, s3, s4);
    if (o1 < s4) ins5key(o1, s0, s1, s2, s3, s4);
    if (o2 < s4) ins5key(o2, s0, s1, s2, s3, s4);
    if (o3 < s4) ins5key(o3, s0, s1, s2, s3, s4);
    if (o4 < s4) ins5key(o4, s0, s1, s2, s3, s4);
}

__device__ __forceinline__ unsigned long long packf2(float lo, float hi) {
    unsigned long long r;
    asm("mov.b64 %0, {%1, %2};" : "=l"(r) : "f"(lo), "f"(hi));
    return r;
}

__global__ __launch_bounds__(T1)
void knn_main(const float* __restrict__ src,
              const float* __restrict__ tgt,
              const float* __restrict__ noise)
{
    // Pair-SoA layout: sC[2p] = {x_2p, x_2p+1, y_2p, y_2p+1},
    //                  sC[2p+1] = {z_2p, z_2p+1, |q|^2_2p, |q|^2_2p+1}
    __shared__ float4 sC[NPTS];      // 32 KB

    const int tid   = threadIdx.x;
    const int cloud = blockIdx.y;
    const float* __restrict__ pts = cloud ? src : tgt;

    for (int i = tid; i < NPTS; i += T1) {
        float x = pts[3*i], y = pts[3*i+1], z = pts[3*i+2];
        float w = fmaf(x, x, fmaf(y, y, z * z));
        int pj = i >> 1, h = i & 1;
        float* base = (float*)&sC[2 * pj];
        base[0 + h] = x;
        base[2 + h] = y;
        base[4 + h] = z;
        base[6 + h] = w;
    }
    __syncthreads();

    const int qi  = blockIdx.x * QPB + (tid >> 2);
    const int par = tid & 3;

    // Build query point.
    float qx, qy, qz;
    if (qi < NJIT) {
        int m = qi / UPR;
        qx = fmaf(noise[3*qi + 0], STDV, tgt[3*m + 0]);
        qy = fmaf(noise[3*qi + 1], STDV, tgt[3*m + 1]);
        qz = fmaf(noise[3*qi + 2], STDV, tgt[3*m + 2]);
    } else {
        int m = qi - NJIT;
        qx = src[3*m + 0]; qy = src[3*m + 1]; qz = src[3*m + 2];
    }
    const float qx2 = -2.0f * qx, qy2 = -2.0f * qy, qz2 = -2.0f * qz;
    const float q2  = fmaf(qx, qx, fmaf(qy, qy, qz * qz));
    const unsigned long long qxp = packf2(qx2, qx2);
    const unsigned long long qyp = packf2(qy2, qy2);
    const unsigned long long qzp = packf2(qz2, qz2);

    int s0 = 0x7F000000, s1 = 0x7F000001, s2 = 0x7F000002,
        s3 = 0x7F000003, s4 = 0x7F000004;
    float thr = __int_as_float(s4) - q2;   // threshold in r-space

    // Each lane owns pairs pj = 4*k + par  (512 points / lane).
#pragma unroll 4
    for (int k = 0; k < NPAIR / SPLIT; ++k) {
        int pj = (k << 2) + par;
        float4 a = sC[2 * pj];       // {x0,x1,y0,y1}
        float4 b = sC[2 * pj + 1];   // {z0,z1,w0,w1}
        unsigned long long xx = packf2(a.x, a.y);
        unsigned long long yy = packf2(a.z, a.w);
        unsigned long long zz = packf2(b.x, b.y);
        unsigned long long ww = packf2(b.z, b.w);
        unsigned long long r01;
        asm("fma.rn.f32x2 %0, %1, %2, %3;" : "=l"(r01) : "l"(zz), "l"(qzp), "l"(ww));
        asm("fma.rn.f32x2 %0, %1, %2, %3;" : "=l"(r01) : "l"(yy), "l"(qyp), "l"(r01));
        asm("fma.rn.f32x2 %0, %1, %2, %3;" : "=l"(r01) : "l"(xx), "l"(qxp), "l"(r01));
        float r0, r1;
        asm("mov.b64 {%0, %1}, %2;" : "=f"(r0), "=f"(r1) : "l"(r01));

        if (fminf(r0, r1) < thr) {
            if (r0 < thr) {
                float d2 = r0 + q2;   // may be ~-eps for self point: packs negative, sorts first (correct)
                int key = (int)((__float_as_uint(d2) & IDXMASK) | (unsigned)(2 * pj));
                ins5key(key, s0, s1, s2, s3, s4);
                thr = __int_as_float(s4) - q2;
            }
            if (r1 < thr) {
                float d2 = r1 + q2;
                int key = (int)((__float_as_uint(d2) & IDXMASK) | (unsigned)(2 * pj + 1));
                ins5key(key, s0, s1, s2, s3, s4);
                thr = __int_as_float(s4) - q2;
            }
        }
    }

    merge_keys(1, s0, s1, s2, s3, s4);
    merge_keys(2, s0, s1, s2, s3, s4);

    if (par == 0) {
        float aw = 0.f, gx = 0.f, gy = 0.f, gz = 0.f;
        int keys[KNN] = {s0, s1, s2, s3, s4};
#pragma unroll
        for (int kk = 0; kk < KNN; ++kk) {
            int idx = keys[kk] & 2047;
            int pj = idx >> 1, h = idx & 1;
            const float* base = (const float*)&sC[2 * pj];
            float x = base[0 + h], y = base[2 + h], z = base[4 + h];
            float dx = qx - x, dy = qy - y, dz = qz - z;
            float d2 = fmaf(dx, dx, fmaf(dy, dy, dz * dz));   // exact, non-negative
            float w  = 1.0f / (d2 + EPS_D);
            aw += w;
            gx = fmaf(dx, w, gx);
            gy = fmaf(dy, w, gy);
            gz = fmaf(dz, w, gz);
        }
        float inv = 1.0f / aw;
        g_grad[cloud][qi] = make_float4(gx * inv, gy * inv, gz * inv, 0.f);
    }
}

__global__ __launch_bounds__(256)
void combine_kernel()
{
    __shared__ float sh[8];
    const int tid = threadIdx.x;
    const int qi  = blockIdx.x * 256 + tid;

    float4 gT = g_grad[0][qi];
    float4 gS = g_grad[1][qi];

    float axT = gT.x + EPS_N, ayT = gT.y + EPS_N, azT = gT.z + EPS_N;
    float axS = gS.x + EPS_N, ayS = gS.y + EPS_N, azS = gS.z + EPS_N;
    float uT = sqrtf(fmaf(axT, axT, fmaf(ayT, ayT, azT * azT)));
    float uS = sqrtf(fmaf(axS, axS, fmaf(ayS, ayS, azS * azS)));

    float e1 = fabsf(uT - uS);
    float e2 = fabsf(gS.x - gT.x) + fabsf(gS.y - gT.y) + fabsf(gS.z - gT.z);
    float t  = e1 + e2;
    float v  = t * __expf(-BETA * t);

#pragma unroll
    for (int o = 16; o > 0; o >>= 1) v += __shfl_down_sync(0xFFFFFFFFu, v, o);
    if ((tid & 31) == 0) sh[tid >> 5] = v;
    __syncthreads();
    if (tid == 0) {
        float s = 0.f;
#pragma unroll
        for (int w = 0; w < 8; ++w) s += sh[w];
        g_partial[blockIdx.x] = s;
    }
}

__global__ void final_reduce(float* __restrict__ out)
{
    __shared__ float sh[4];
    int tid = threadIdx.x;   // 128
    float v = (tid < NB2) ? g_partial[tid] : 0.f;
#pragma unroll
    for (int o = 16; o > 0; o >>= 1) v += __shfl_down_sync(0xFFFFFFFFu, v, o);
    if ((tid & 31) == 0) sh[tid >> 5] = v;
    __syncthreads();
    if (tid == 0) {
        float s = sh[0] + sh[1] + sh[2] + sh[3];
        out[0] = s * (1.0f / (float)QTOT);
    }
}

extern "C" void kernel_launch(void* const* d_in, const int* in_sizes, int n_in,
                              void* d_out, int out_size)
{
    const float* src   = (const float*)d_in[0];
    const float* tgt   = (const float*)d_in[1];
    const float* noise = (const float*)d_in[2];
    (void)in_sizes; (void)n_in; (void)out_size;

    knn_main<<<dim3(GX1, 2), T1>>>(src, tgt, noise);
    combine_kernel<<<NB2, 256>>>();
    final_reduce<<<1, 128>>>((float*)d_out);
}